// round 1
// baseline (speedup 1.0000x reference)
#include <cuda_runtime.h>
#include <math.h>

// Scratch for per-row losses (B = 65536 rows). __device__ global => no allocation.
#define MAX_ROWS 65536
__device__ float g_rowloss[MAX_ROWS];

__device__ __forceinline__ float warpMax(float v) {
    #pragma unroll
    for (int k = 16; k; k >>= 1) v = fmaxf(v, __shfl_xor_sync(0xffffffffu, v, k));
    return v;
}
__device__ __forceinline__ float warpSum(float v) {
    #pragma unroll
    for (int k = 16; k; k >>= 1) v += __shfl_xor_sync(0xffffffffu, v, k);
    return v;
}

// One CTA per row. C must be divisible by 4 and <= 1024 (C=1000 here).
// 256 threads; thread i owns elements [4i, 4i+4).
__global__ __launch_bounds__(256, 8)
void mvce_row_kernel(const float* __restrict__ out, const float* __restrict__ tgt, int C)
{
    const int row  = blockIdx.x;
    const int tid  = threadIdx.x;
    const int lane = tid & 31;
    const int wid  = tid >> 5;
    const int C4   = C >> 2;              // 250

    __shared__ float sred[8];             // per-warp partials (reused)
    __shared__ float bc[4];               // broadcast: m, S, T, A

    const float4* o4p = reinterpret_cast<const float4*>(out + (size_t)row * C);
    const float4* t4p = reinterpret_cast<const float4*>(tgt + (size_t)row * C);

    const bool valid = tid < C4;
    float4 o = make_float4(0.f, 0.f, 0.f, 0.f);
    float4 t = make_float4(0.f, 0.f, 0.f, 0.f);
    if (valid) { o = o4p[tid]; t = t4p[tid]; }

    // ---- Pass 1: row max ----
    float lm = valid ? fmaxf(fmaxf(o.x, o.y), fmaxf(o.z, o.w)) : -INFINITY;
    lm = warpMax(lm);
    if (lane == 0) sred[wid] = lm;
    __syncthreads();
    if (tid < 8) {
        float v = sred[tid];
        #pragma unroll
        for (int k = 4; k; k >>= 1) v = fmaxf(v, __shfl_xor_sync(0xffu, v, k));
        if (tid == 0) bc[0] = v;
    }
    __syncthreads();
    const float m = bc[0];

    // ---- Pass 2: negative-set stats (e kept in registers) ----
    float e0 = 0.f, e1 = 0.f, e2 = 0.f, e3 = 0.f;
    float S = 0.f, T = 0.f, A = 0.f;
    if (valid) {
        e0 = __expf(o.x - m); e1 = __expf(o.y - m);
        e2 = __expf(o.z - m); e3 = __expf(o.w - m);
        if (t.x <= 0.5f) { S += e0; T += t.x; A += t.x * o.x; }
        if (t.y <= 0.5f) { S += e1; T += t.y; A += t.y * o.y; }
        if (t.z <= 0.5f) { S += e2; T += t.z; A += t.z * o.z; }
        if (t.w <= 0.5f) { S += e3; T += t.w; A += t.w * o.w; }
    }
    S = warpSum(S); T = warpSum(T); A = warpSum(A);
    if (lane == 0) sred[wid] = S;
    __syncthreads();
    if (tid < 8) {
        float v = sred[tid];
        #pragma unroll
        for (int k = 4; k; k >>= 1) v += __shfl_xor_sync(0xffu, v, k);
        if (tid == 0) bc[1] = v;
    }
    __syncthreads();
    if (lane == 0) sred[wid] = T;
    __syncthreads();
    if (tid < 8) {
        float v = sred[tid];
        #pragma unroll
        for (int k = 4; k; k >>= 1) v += __shfl_xor_sync(0xffu, v, k);
        if (tid == 0) bc[2] = v;
    }
    __syncthreads();
    if (lane == 0) sred[wid] = A;
    __syncthreads();
    if (tid < 8) {
        float v = sred[tid];
        #pragma unroll
        for (int k = 4; k; k >>= 1) v += __shfl_xor_sync(0xffu, v, k);
        if (tid == 0) bc[3] = v;
    }
    __syncthreads();
    const float Sneg = bc[1], Tneg = bc[2], Aneg = bc[3];

    // ---- Pass 3: per-positive loss ----
    float pl = 0.f, np = 0.f;
    if (valid) {
        if (t.x > 0.5f) { pl += (Tneg + t.x) * (m + __logf(Sneg + e0)) - Aneg - t.x * o.x; np += 1.f; }
        if (t.y > 0.5f) { pl += (Tneg + t.y) * (m + __logf(Sneg + e1)) - Aneg - t.y * o.y; np += 1.f; }
        if (t.z > 0.5f) { pl += (Tneg + t.z) * (m + __logf(Sneg + e2)) - Aneg - t.z * o.z; np += 1.f; }
        if (t.w > 0.5f) { pl += (Tneg + t.w) * (m + __logf(Sneg + e3)) - Aneg - t.w * o.w; np += 1.f; }
    }
    pl = warpSum(pl); np = warpSum(np);
    if (lane == 0) sred[wid] = pl;
    __syncthreads();
    float plTot = 0.f, npTot = 0.f;
    if (tid < 8) {
        float v = sred[tid];
        #pragma unroll
        for (int k = 4; k; k >>= 1) v += __shfl_xor_sync(0xffu, v, k);
        plTot = v;
    }
    __syncthreads();
    if (lane == 0) sred[wid] = np;
    __syncthreads();
    if (tid < 8) {
        float v = sred[tid];
        #pragma unroll
        for (int k = 4; k; k >>= 1) v += __shfl_xor_sync(0xffu, v, k);
        npTot = v;
    }

    if (tid == 0) {
        float rl;
        if (npTot > 0.f) {
            rl = plTot / npTot;
        } else {
            rl = Tneg * (m + __logf(Sneg)) - Aneg;   // no-positive fallback
        }
        g_rowloss[row] = rl;
    }
}

// Deterministic final reduction: single block sums all row losses, divides by B.
__global__ __launch_bounds__(1024)
void mvce_final_kernel(float* __restrict__ result, int B)
{
    __shared__ float s[32];
    const int tid  = threadIdx.x;
    const int lane = tid & 31;
    const int wid  = tid >> 5;

    float acc = 0.f;
    for (int i = tid; i < B; i += 1024) acc += g_rowloss[i];
    acc = warpSum(acc);
    if (lane == 0) s[wid] = acc;
    __syncthreads();
    if (tid < 32) {
        float v = s[tid];
        v = warpSum(v);
        if (tid == 0) result[0] = v / (float)B;
    }
}

extern "C" void kernel_launch(void* const* d_in, const int* in_sizes, int n_in,
                              void* d_out, int out_size)
{
    const float* output = (const float*)d_in[0];
    const float* target = (const float*)d_in[1];
    float* result = (float*)d_out;

    const int C = 1000;
    const int B = in_sizes[0] / C;

    mvce_row_kernel<<<B, 256>>>(output, target, C);
    mvce_final_kernel<<<1, 1024>>>(result, B);
}